// round 1
// baseline (speedup 1.0000x reference)
#include <cuda_runtime.h>
#include <stdint.h>

#define N_NODES 200000
#define N_DIM   64
#define N_EDGES 6400000
#define D2      (N_DIM / 2)   // 32 float2 per row == one per lane

// ---------------- static scratch (no allocations allowed) ----------------
__device__ unsigned long long g_edges[N_EDGES];        // packed (col, val) sorted by row
__device__ int   g_counts[N_NODES];
__device__ int   g_row_ptr[N_NODES];
__device__ int   g_cursor[N_NODES];
__device__ float g_h[2][N_NODES * N_DIM];              // ping-pong layer embeddings

// ---------------- CSR build ----------------
__global__ void zero_counts_kernel() {
    int i = blockIdx.x * blockDim.x + threadIdx.x;
    if (i < N_NODES) g_counts[i] = 0;
}

__global__ void histogram_kernel(const int* __restrict__ rows) {
    int e = blockIdx.x * blockDim.x + threadIdx.x;
    if (e < N_EDGES) atomicAdd(&g_counts[rows[e]], 1);
}

// Single-block exclusive scan over 200000 counts (1024 threads x 196 chunk).
__global__ void scan_kernel() {
    __shared__ int sh[1024];
    const int t = threadIdx.x;
    const int CHUNK = (N_NODES + 1023) / 1024;   // 196
    const int base = t * CHUNK;

    int s = 0;
    for (int i = 0; i < CHUNK; i++) {
        int idx = base + i;
        if (idx < N_NODES) s += g_counts[idx];
    }
    sh[t] = s;
    __syncthreads();

    // Hillis-Steele inclusive scan over 1024 partials
    for (int off = 1; off < 1024; off <<= 1) {
        int v = sh[t];
        int add = (t >= off) ? sh[t - off] : 0;
        __syncthreads();
        sh[t] = v + add;
        __syncthreads();
    }
    int run = (t == 0) ? 0 : sh[t - 1];   // exclusive offset for this chunk

    for (int i = 0; i < CHUNK; i++) {
        int idx = base + i;
        if (idx < N_NODES) {
            g_row_ptr[idx] = run;
            g_cursor[idx]  = run;
            run += g_counts[idx];
        }
    }
}

__global__ void scatter_kernel(const int* __restrict__ rows,
                               const int* __restrict__ cols,
                               const float* __restrict__ vals) {
    int e = blockIdx.x * blockDim.x + threadIdx.x;
    if (e < N_EDGES) {
        int r = rows[e];
        int p = atomicAdd(&g_cursor[r], 1);
        unsigned long long pk = (unsigned long long)(unsigned)cols[e]
                              | ((unsigned long long)__float_as_uint(vals[e]) << 32);
        g_edges[p] = pk;
    }
}

// ---------------- row-parallel SpMM (one warp per row) ----------------
// layer 1: out = x(=emb) + acc ; y = acc
// layer 2: out += acc          ; y = acc
// layer 3: out = (out + acc) * 0.25 ; y unused
__global__ void spmm_kernel(const float2* __restrict__ x,
                            float2* __restrict__ y,
                            float2* __restrict__ out,
                            int layer) {
    int wid  = (blockIdx.x * blockDim.x + threadIdx.x) >> 5;
    int lane = threadIdx.x & 31;
    if (wid >= N_NODES) return;

    const int start = g_row_ptr[wid];
    const int deg   = g_counts[wid];
    const unsigned long long* ep = g_edges + start;

    float2 acc = make_float2(0.f, 0.f);
    #pragma unroll 4
    for (int i = 0; i < deg; i++) {
        unsigned long long pk = __ldg(ep + i);
        int   c = (int)(unsigned)(pk & 0xffffffffull);
        float v = __uint_as_float((unsigned)(pk >> 32));
        float2 xv = __ldg(&x[c * D2 + lane]);
        acc.x = fmaf(v, xv.x, acc.x);
        acc.y = fmaf(v, xv.y, acc.y);
    }

    const int o = wid * D2 + lane;
    if (layer == 1) {
        float2 e0 = __ldg(&x[o]);          // x == emb here
        out[o] = make_float2(e0.x + acc.x, e0.y + acc.y);
        y[o] = acc;
    } else if (layer == 2) {
        float2 t = out[o];
        out[o] = make_float2(t.x + acc.x, t.y + acc.y);
        y[o] = acc;
    } else {
        float2 t = out[o];
        out[o] = make_float2((t.x + acc.x) * 0.25f, (t.y + acc.y) * 0.25f);
    }
}

extern "C" void kernel_launch(void* const* d_in, const int* in_sizes, int n_in,
                              void* d_out, int out_size) {
    const float* emb  = (const float*)d_in[0];
    const float* vals = (const float*)d_in[1];
    const int*   rows = (const int*)d_in[2];
    const int*   cols = (const int*)d_in[3];
    float2* out = (float2*)d_out;

    float2* h0;  // device addresses of static buffers
    float2* h1;
    cudaGetSymbolAddress((void**)&h0, g_h);
    h1 = h0 + (size_t)N_NODES * D2;

    const int TB = 256;

    // ---- build CSR ----
    zero_counts_kernel<<<(N_NODES + TB - 1) / TB, TB>>>();
    histogram_kernel<<<(N_EDGES + TB - 1) / TB, TB>>>(rows);
    scan_kernel<<<1, 1024>>>();
    scatter_kernel<<<(N_EDGES + TB - 1) / TB, TB>>>(rows, cols, vals);

    // ---- 3 propagation layers, one warp per row ----
    const int warps_per_block = TB / 32;
    const int grid = (N_NODES + warps_per_block - 1) / warps_per_block;

    spmm_kernel<<<grid, TB>>>((const float2*)emb, h0, out, 1);
    spmm_kernel<<<grid, TB>>>((const float2*)h0,  h1, out, 2);
    spmm_kernel<<<grid, TB>>>((const float2*)h1,  h1, out, 3);
}

// round 2
// speedup vs baseline: 1.6568x; 1.6568x over previous
#include <cuda_runtime.h>
#include <cuda_fp16.h>
#include <stdint.h>

#define N_NODES 200000
#define N_DIM   64
#define N_EDGES 6400000
#define D2      (N_DIM / 2)                 // 32 half2 (or float2) per row, one per lane
#define NB      ((N_NODES + 255) / 256)     // 782 blocks of 256 nodes

// ---------------- static scratch (no allocations allowed) ----------------
__device__ unsigned long long g_edges[N_EDGES];   // packed (col, fp32 val), CSR order
__device__ int   g_counts[N_NODES];
__device__ int   g_row_ptr[N_NODES];
__device__ int   g_cursor[N_NODES];
__device__ int   g_block_sums[NB];
__device__ int   g_block_offs[NB];
__device__ __half2 g_e [N_NODES * D2];            // fp16 copy of emb
__device__ __half2 g_h1[N_NODES * D2];            // layer-1 output (fp16)
__device__ __half2 g_h2[N_NODES * D2];            // layer-2 output (fp16)

// ---------------- CSR build ----------------
__global__ void zero_counts_kernel() {
    int i = blockIdx.x * blockDim.x + threadIdx.x;
    if (i < N_NODES) g_counts[i] = 0;
}

__global__ void histogram_kernel(const int* __restrict__ rows) {
    int e = blockIdx.x * blockDim.x + threadIdx.x;
    if (e < N_EDGES) atomicAdd(&g_counts[rows[e]], 1);
}

// fp32 emb -> fp16 (one half2 per thread)
__global__ void convert_kernel(const float2* __restrict__ emb) {
    int i = blockIdx.x * blockDim.x + threadIdx.x;
    if (i < N_NODES * D2) g_e[i] = __float22half2_rn(emb[i]);
}

// scan stage 1: per-256-block sums (coalesced)
__global__ void scan_reduce_kernel() {
    int b = blockIdx.x, t = threadIdx.x;
    int idx = b * 256 + t;
    int v = (idx < N_NODES) ? g_counts[idx] : 0;
    // warp reduce
    for (int o = 16; o > 0; o >>= 1) v += __shfl_down_sync(0xffffffffu, v, o);
    __shared__ int ws[8];
    if ((t & 31) == 0) ws[t >> 5] = v;
    __syncthreads();
    if (t == 0) {
        int s = 0;
        #pragma unroll
        for (int i = 0; i < 8; i++) s += ws[i];
        g_block_sums[b] = s;
    }
}

// scan stage 2: exclusive scan of NB (=782) block sums in one block
__global__ void scan_partials_kernel() {
    __shared__ int sh[1024];
    int t = threadIdx.x;
    int v = (t < NB) ? g_block_sums[t] : 0;
    sh[t] = v;
    __syncthreads();
    for (int off = 1; off < 1024; off <<= 1) {
        int x = sh[t];
        int add = (t >= off) ? sh[t - off] : 0;
        __syncthreads();
        sh[t] = x + add;
        __syncthreads();
    }
    if (t < NB) g_block_offs[t] = sh[t] - v;   // exclusive
}

// scan stage 3: block-local exclusive scan + global offset -> row_ptr / cursor
__global__ void scan_apply_kernel() {
    int b = blockIdx.x, t = threadIdx.x;
    int idx = b * 256 + t;
    int v = (idx < N_NODES) ? g_counts[idx] : 0;
    int lane = t & 31, w = t >> 5;
    int x = v;
    #pragma unroll
    for (int o = 1; o < 32; o <<= 1) {
        int y = __shfl_up_sync(0xffffffffu, x, o);
        if (lane >= o) x += y;
    }
    __shared__ int wsum[8];
    __shared__ int woff[8];
    if (lane == 31) wsum[w] = x;
    __syncthreads();
    if (t == 0) {
        int run = 0;
        #pragma unroll
        for (int i = 0; i < 8; i++) { woff[i] = run; run += wsum[i]; }
    }
    __syncthreads();
    int excl = x - v + woff[w] + g_block_offs[b];
    if (idx < N_NODES) {
        g_row_ptr[idx] = excl;
        g_cursor[idx]  = excl;
    }
}

__global__ void scatter_kernel(const int* __restrict__ rows,
                               const int* __restrict__ cols,
                               const float* __restrict__ vals) {
    int e = blockIdx.x * blockDim.x + threadIdx.x;
    if (e < N_EDGES) {
        int r = rows[e];
        int p = atomicAdd(&g_cursor[r], 1);
        unsigned long long pk = (unsigned long long)(unsigned)cols[e]
                              | ((unsigned long long)__float_as_uint(vals[e]) << 32);
        g_edges[p] = pk;
    }
}

// ---------------- row-parallel SpMM (one warp per row, fp16 gather) ----------------
// LAYER 1: y(h1) = A * e_half
// LAYER 2: y(h2) = A * h1
// LAYER 3: out = (emb + h1 + h2 + A*h2) * 0.25
template<int LAYER>
__global__ void spmm_kernel(const __half2* __restrict__ x,
                            __half2* __restrict__ y,
                            const float2* __restrict__ emb,
                            float2* __restrict__ out) {
    int wid  = (blockIdx.x * blockDim.x + threadIdx.x) >> 5;
    int lane = threadIdx.x & 31;
    if (wid >= N_NODES) return;

    const int start = g_row_ptr[wid];
    const int deg   = g_counts[wid];
    const unsigned long long* ep = g_edges + start;

    float2 acc = make_float2(0.f, 0.f);
    #pragma unroll 8
    for (int i = 0; i < deg; i++) {
        unsigned long long pk = __ldg(ep + i);
        int   c = (int)(unsigned)(pk & 0xffffffffull);
        float v = __uint_as_float((unsigned)(pk >> 32));
        float2 xv = __half22float2(__ldg(&x[c * D2 + lane]));
        acc.x = fmaf(v, xv.x, acc.x);
        acc.y = fmaf(v, xv.y, acc.y);
    }

    const int o = wid * D2 + lane;
    if (LAYER < 3) {
        y[o] = __float22half2_rn(acc);
    } else {
        float2 e0 = __ldg(&emb[o]);
        float2 a1 = __half22float2(__ldg(&g_h1[o]));
        float2 a2 = __half22float2(__ldg(&g_h2[o]));
        out[o] = make_float2((e0.x + a1.x + a2.x + acc.x) * 0.25f,
                             (e0.y + a1.y + a2.y + acc.y) * 0.25f);
    }
}

extern "C" void kernel_launch(void* const* d_in, const int* in_sizes, int n_in,
                              void* d_out, int out_size) {
    const float* emb  = (const float*)d_in[0];
    const float* vals = (const float*)d_in[1];
    const int*   rows = (const int*)d_in[2];
    const int*   cols = (const int*)d_in[3];
    float2* out = (float2*)d_out;

    __half2* he;  __half2* h1;  __half2* h2;
    cudaGetSymbolAddress((void**)&he, g_e);
    cudaGetSymbolAddress((void**)&h1, g_h1);
    cudaGetSymbolAddress((void**)&h2, g_h2);

    const int TB = 256;

    // ---- build CSR + fp16 copy of emb ----
    zero_counts_kernel<<<NB, TB>>>();
    histogram_kernel<<<(N_EDGES + TB - 1) / TB, TB>>>(rows);
    convert_kernel<<<(N_NODES * D2 + TB - 1) / TB, TB>>>((const float2*)emb);
    scan_reduce_kernel<<<NB, TB>>>();
    scan_partials_kernel<<<1, 1024>>>();
    scan_apply_kernel<<<NB, TB>>>();
    scatter_kernel<<<(N_EDGES + TB - 1) / TB, TB>>>(rows, cols, vals);

    // ---- 3 propagation layers, one warp per row ----
    const int warps_per_block = TB / 32;
    const int grid = (N_NODES + warps_per_block - 1) / warps_per_block;

    spmm_kernel<1><<<grid, TB>>>(he, h1, (const float2*)emb, out);
    spmm_kernel<2><<<grid, TB>>>(h1, h2, (const float2*)emb, out);
    spmm_kernel<3><<<grid, TB>>>(h2, nullptr, (const float2*)emb, out);
}

// round 3
// speedup vs baseline: 1.7521x; 1.0576x over previous
#include <cuda_runtime.h>
#include <cuda_fp16.h>
#include <stdint.h>

#define N_NODES 200000
#define N_DIM   64
#define N_EDGES 6400000
#define D2      (N_DIM / 2)                 // 32 half2 per row
#define ROW_U4  8                           // 8 uint4 (16B) chunks per fp16 row
#define NB      ((N_NODES + 255) / 256)     // 782 blocks of 256 nodes

// ---------------- static scratch (no allocations allowed) ----------------
__device__ unsigned long long g_edges[N_EDGES];   // packed (col, fp32 val), CSR order
__device__ int   g_counts[N_NODES];
__device__ int   g_row_ptr[N_NODES];
__device__ int   g_cursor[N_NODES];
__device__ int   g_block_sums[NB];
__device__ int   g_block_offs[NB];
__device__ __align__(128) __half2 g_e [N_NODES * D2];   // fp16 copy of emb
__device__ __align__(128) __half2 g_h1[N_NODES * D2];   // layer-1 output (fp16)
__device__ __align__(128) __half2 g_h2[N_NODES * D2];   // layer-2 output (fp16)

// ---------------- CSR build ----------------
__global__ void zero_counts_kernel() {
    int i = blockIdx.x * blockDim.x + threadIdx.x;
    if (i < N_NODES) g_counts[i] = 0;
}

__global__ void histogram_kernel(const int* __restrict__ rows) {
    int e = blockIdx.x * blockDim.x + threadIdx.x;
    if (e < N_EDGES) atomicAdd(&g_counts[rows[e]], 1);
}

// fp32 emb -> fp16 (one half2 per thread)
__global__ void convert_kernel(const float2* __restrict__ emb) {
    int i = blockIdx.x * blockDim.x + threadIdx.x;
    if (i < N_NODES * D2) g_e[i] = __float22half2_rn(emb[i]);
}

// scan stage 1: per-256-block sums (coalesced)
__global__ void scan_reduce_kernel() {
    int b = blockIdx.x, t = threadIdx.x;
    int idx = b * 256 + t;
    int v = (idx < N_NODES) ? g_counts[idx] : 0;
    for (int o = 16; o > 0; o >>= 1) v += __shfl_down_sync(0xffffffffu, v, o);
    __shared__ int ws[8];
    if ((t & 31) == 0) ws[t >> 5] = v;
    __syncthreads();
    if (t == 0) {
        int s = 0;
        #pragma unroll
        for (int i = 0; i < 8; i++) s += ws[i];
        g_block_sums[b] = s;
    }
}

// scan stage 2: exclusive scan of NB block sums in one block
__global__ void scan_partials_kernel() {
    __shared__ int sh[1024];
    int t = threadIdx.x;
    int v = (t < NB) ? g_block_sums[t] : 0;
    sh[t] = v;
    __syncthreads();
    for (int off = 1; off < 1024; off <<= 1) {
        int x = sh[t];
        int add = (t >= off) ? sh[t - off] : 0;
        __syncthreads();
        sh[t] = x + add;
        __syncthreads();
    }
    if (t < NB) g_block_offs[t] = sh[t] - v;   // exclusive
}

// scan stage 3: block-local exclusive scan + global offset -> row_ptr / cursor
__global__ void scan_apply_kernel() {
    int b = blockIdx.x, t = threadIdx.x;
    int idx = b * 256 + t;
    int v = (idx < N_NODES) ? g_counts[idx] : 0;
    int lane = t & 31, w = t >> 5;
    int x = v;
    #pragma unroll
    for (int o = 1; o < 32; o <<= 1) {
        int y = __shfl_up_sync(0xffffffffu, x, o);
        if (lane >= o) x += y;
    }
    __shared__ int wsum[8];
    __shared__ int woff[8];
    if (lane == 31) wsum[w] = x;
    __syncthreads();
    if (t == 0) {
        int run = 0;
        #pragma unroll
        for (int i = 0; i < 8; i++) { woff[i] = run; run += wsum[i]; }
    }
    __syncthreads();
    int excl = x - v + woff[w] + g_block_offs[b];
    if (idx < N_NODES) {
        g_row_ptr[idx] = excl;
        g_cursor[idx]  = excl;
    }
}

__global__ void scatter_kernel(const int* __restrict__ rows,
                               const int* __restrict__ cols,
                               const float* __restrict__ vals) {
    int e = blockIdx.x * blockDim.x + threadIdx.x;
    if (e < N_EDGES) {
        int r = rows[e];
        int p = atomicAdd(&g_cursor[r], 1);
        unsigned long long pk = (unsigned long long)(unsigned)cols[e]
                              | ((unsigned long long)__float_as_uint(vals[e]) << 32);
        g_edges[p] = pk;
    }
}

// ---------------- row-parallel SpMM: 1 warp per row, 4 edges per iteration ----------------
// lane = g*8 + s ; g = which edge of the quad ; s = which 16B chunk of the 128B row
// LAYER 1: h1 = A * e_half
// LAYER 2: h2 = A * h1
// LAYER 3: out = (emb + h1 + h2 + A*h2) * 0.25   (fp32 out)
template<int LAYER>
__global__ void spmm_kernel(const uint4* __restrict__ x,     // fp16 rows
                            uint4* __restrict__ y,           // fp16 rows (layers 1,2)
                            const float4* __restrict__ emb,  // fp32 (layer 3)
                            float4* __restrict__ out) {
    int wid  = (blockIdx.x * blockDim.x + threadIdx.x) >> 5;
    int lane = threadIdx.x & 31;
    if (wid >= N_NODES) return;
    const int g = lane >> 3;      // 0..3 : edge slot
    const int s = lane & 7;       // 0..7 : row chunk

    const int start = g_row_ptr[wid];
    const int deg   = g_counts[wid];
    const unsigned long long* ep = g_edges + start;

    float a0 = 0.f, a1 = 0.f, a2 = 0.f, a3 = 0.f,
          a4 = 0.f, a5 = 0.f, a6 = 0.f, a7 = 0.f;

    const int iters = (deg + 3) >> 2;
    for (int i = 0; i < iters; i++) {
        const int e = (i << 2) + g;
        const bool ok = (e < deg);
        unsigned long long pk = ok ? __ldg(ep + e) : 0ull;
        const int   c = (int)(unsigned)(pk & 0xffffffffull);
        const float v = ok ? __uint_as_float((unsigned)(pk >> 32)) : 0.f;
        uint4 q = make_uint4(0u, 0u, 0u, 0u);
        if (ok) q = __ldg(&x[c * ROW_U4 + s]);
        const float2 f0 = __half22float2(*(const __half2*)&q.x);
        const float2 f1 = __half22float2(*(const __half2*)&q.y);
        const float2 f2 = __half22float2(*(const __half2*)&q.z);
        const float2 f3 = __half22float2(*(const __half2*)&q.w);
        a0 = fmaf(v, f0.x, a0);  a1 = fmaf(v, f0.y, a1);
        a2 = fmaf(v, f1.x, a2);  a3 = fmaf(v, f1.y, a3);
        a4 = fmaf(v, f2.x, a4);  a5 = fmaf(v, f2.y, a5);
        a6 = fmaf(v, f3.x, a6);  a7 = fmaf(v, f3.y, a7);
    }

    // combine the 4 edge-groups: xor 8 then xor 16 (s is preserved)
    #pragma unroll
    for (int off = 8; off <= 16; off <<= 1) {
        a0 += __shfl_xor_sync(0xffffffffu, a0, off);
        a1 += __shfl_xor_sync(0xffffffffu, a1, off);
        a2 += __shfl_xor_sync(0xffffffffu, a2, off);
        a3 += __shfl_xor_sync(0xffffffffu, a3, off);
        a4 += __shfl_xor_sync(0xffffffffu, a4, off);
        a5 += __shfl_xor_sync(0xffffffffu, a5, off);
        a6 += __shfl_xor_sync(0xffffffffu, a6, off);
        a7 += __shfl_xor_sync(0xffffffffu, a7, off);
    }

    if (g == 0) {   // lanes 0..7 write the row
        if (LAYER < 3) {
            __half2 h0 = __floats2half2_rn(a0, a1);
            __half2 h1 = __floats2half2_rn(a2, a3);
            __half2 h2 = __floats2half2_rn(a4, a5);
            __half2 h3 = __floats2half2_rn(a6, a7);
            uint4 q;
            q.x = *(unsigned*)&h0;  q.y = *(unsigned*)&h1;
            q.z = *(unsigned*)&h2;  q.w = *(unsigned*)&h3;
            y[wid * ROW_U4 + s] = q;
        } else {
            const uint4 q1 = __ldg((const uint4*)g_h1 + wid * ROW_U4 + s);
            const uint4 q2 = __ldg((const uint4*)g_h2 + wid * ROW_U4 + s);
            const float2 b0 = __half22float2(*(const __half2*)&q1.x);
            const float2 b1 = __half22float2(*(const __half2*)&q1.y);
            const float2 b2 = __half22float2(*(const __half2*)&q1.z);
            const float2 b3 = __half22float2(*(const __half2*)&q1.w);
            const float2 c0 = __half22float2(*(const __half2*)&q2.x);
            const float2 c1 = __half22float2(*(const __half2*)&q2.y);
            const float2 c2 = __half22float2(*(const __half2*)&q2.z);
            const float2 c3 = __half22float2(*(const __half2*)&q2.w);
            const float4 e0 = __ldg(&emb[wid * 16 + s * 2 + 0]);
            const float4 e1 = __ldg(&emb[wid * 16 + s * 2 + 1]);
            float4 o0, o1;
            o0.x = (e0.x + b0.x + c0.x + a0) * 0.25f;
            o0.y = (e0.y + b0.y + c0.y + a1) * 0.25f;
            o0.z = (e0.z + b1.x + c1.x + a2) * 0.25f;
            o0.w = (e0.w + b1.y + c1.y + a3) * 0.25f;
            o1.x = (e1.x + b2.x + c2.x + a4) * 0.25f;
            o1.y = (e1.y + b2.y + c2.y + a5) * 0.25f;
            o1.z = (e1.z + b3.x + c3.x + a6) * 0.25f;
            o1.w = (e1.w + b3.y + c3.y + a7) * 0.25f;
            out[wid * 16 + s * 2 + 0] = o0;
            out[wid * 16 + s * 2 + 1] = o1;
        }
    }
}

extern "C" void kernel_launch(void* const* d_in, const int* in_sizes, int n_in,
                              void* d_out, int out_size) {
    const float* emb  = (const float*)d_in[0];
    const float* vals = (const float*)d_in[1];
    const int*   rows = (const int*)d_in[2];
    const int*   cols = (const int*)d_in[3];
    float4* out = (float4*)d_out;

    uint4* he;  uint4* h1;  uint4* h2;
    cudaGetSymbolAddress((void**)&he, g_e);
    cudaGetSymbolAddress((void**)&h1, g_h1);
    cudaGetSymbolAddress((void**)&h2, g_h2);

    const int TB = 256;

    // ---- build CSR + fp16 copy of emb ----
    zero_counts_kernel<<<NB, TB>>>();
    histogram_kernel<<<(N_EDGES + TB - 1) / TB, TB>>>(rows);
    convert_kernel<<<(N_NODES * D2 + TB - 1) / TB, TB>>>((const float2*)emb);
    scan_reduce_kernel<<<NB, TB>>>();
    scan_partials_kernel<<<1, 1024>>>();
    scan_apply_kernel<<<NB, TB>>>();
    scatter_kernel<<<(N_EDGES + TB - 1) / TB, TB>>>(rows, cols, vals);

    // ---- 3 propagation layers, one warp per row ----
    const int warps_per_block = TB / 32;
    const int grid = (N_NODES + warps_per_block - 1) / warps_per_block;

    spmm_kernel<1><<<grid, TB>>>(he, h1, (const float4*)emb, out);
    spmm_kernel<2><<<grid, TB>>>(h1, h2, (const float4*)emb, out);
    spmm_kernel<3><<<grid, TB>>>(h2, nullptr, (const float4*)emb, out);
}